// round 17
// baseline (speedup 1.0000x reference)
#include <cuda_runtime.h>
#include <cuda_bf16.h>
#include <cuda_fp16.h>
#include <cstdint>

// ===========================================================================
// VQ-VAE forward on GB300:
//   encoder   : fp16 2-plane HMMA, 3 products, fragment-reuse inner loop
//               (fp16 OK: encoder activations are in fp16 normal range)
//   decoder   : bf16 2-plane HMMA, 3 products, fragment-reuse inner loop
//               (bf16 REQUIRED: decoder activations ~1e-5 hit fp16 subnormal
//                cliff -> bf16's fp32 exponent range avoids it; round-13 proven)
//   VQ        : fp32 distances + gap test -> flags (T=1e-8)
//   repair    : BATCHED exact-fp32 recompute of flagged rows (proven)
// ===========================================================================

#define M_ROWS 8192
#define EMB_NUM 1024
#define EMB_DIM 64
#define FLAG_T 1e-8f
#define REP_CAP 2048

typedef unsigned long long u64;
typedef __nv_bfloat16 bf16;
typedef __half f16;

// ---------------------------------------------------------------------------
// Static device scratch (allocation-free rule)
// ---------------------------------------------------------------------------
__device__ f16  g_xh[8192 * 2048];
__device__ f16  g_xm[8192 * 2048];
__device__ f16  g_w0h[1024 * 2048];
__device__ f16  g_w0m[1024 * 2048];
__device__ f16  g_w1h[512 * 1024];
__device__ f16  g_w1m[512 * 1024];
__device__ f16  g_wzh[256 * 512];
__device__ f16  g_wzm[256 * 512];
__device__ f16  g_h1h[8192 * 1024];
__device__ f16  g_h1m[8192 * 1024];
__device__ f16  g_h2h[8192 * 512];
__device__ f16  g_h2m[8192 * 512];
__device__ float g_z [8192 * 256];
__device__ float g_cn[EMB_NUM];
__device__ int   g_flags[32768];
__device__ int   g_rlist[M_ROWS];
__device__ int   g_nrep;
__device__ float g_rh1[REP_CAP * 1024];
__device__ float g_rh2[REP_CAP * 512];
__device__ bf16 g_zq[2][8192 * 256];
__device__ bf16 g_d1[2][8192 * 512];
__device__ bf16 g_d2[2][8192 * 1024];
__device__ bf16 g_wd0[2][512 * 256];
__device__ bf16 g_wd1[2][1024 * 512];
__device__ bf16 g_wo[2][2048 * 1024];

// ---------------------------------------------------------------------------
// PTX helpers
// ---------------------------------------------------------------------------
__device__ __forceinline__ uint32_t smem_u32(const void* p) {
    uint32_t a;
    asm("{ .reg .u64 t; cvta.to.shared.u64 t, %1; cvt.u32.u64 %0, t; }" : "=r"(a) : "l"(p));
    return a;
}
__device__ __forceinline__ void cp16(uint32_t dst, const void* src) {
    asm volatile("cp.async.cg.shared.global [%0], [%1], 16;" :: "r"(dst), "l"(src));
}
#define CP_COMMIT() asm volatile("cp.async.commit_group;" ::: "memory")
#define CP_WAIT0()  asm volatile("cp.async.wait_group 0;" ::: "memory")

__device__ __forceinline__ void ldm_x4(uint32_t r[4], uint32_t addr) {
    asm volatile("ldmatrix.sync.aligned.m8n8.x4.shared.b16 {%0,%1,%2,%3}, [%4];"
                 : "=r"(r[0]), "=r"(r[1]), "=r"(r[2]), "=r"(r[3]) : "r"(addr));
}
__device__ __forceinline__ void mma_bf16(float* d, const uint32_t* a, uint32_t b0, uint32_t b1) {
    asm volatile(
        "mma.sync.aligned.m16n8k16.row.col.f32.bf16.bf16.f32 "
        "{%0,%1,%2,%3}, {%4,%5,%6,%7}, {%8,%9}, {%0,%1,%2,%3};"
        : "+f"(d[0]), "+f"(d[1]), "+f"(d[2]), "+f"(d[3])
        : "r"(a[0]), "r"(a[1]), "r"(a[2]), "r"(a[3]), "r"(b0), "r"(b1));
}
__device__ __forceinline__ void mma_f16(float* d, const uint32_t* a, uint32_t b0, uint32_t b1) {
    asm volatile(
        "mma.sync.aligned.m16n8k16.row.col.f32.f16.f16.f32 "
        "{%0,%1,%2,%3}, {%4,%5,%6,%7}, {%8,%9}, {%0,%1,%2,%3};"
        : "+f"(d[0]), "+f"(d[1]), "+f"(d[2]), "+f"(d[3])
        : "r"(a[0]), "r"(a[1]), "r"(a[2]), "r"(a[3]), "r"(b0), "r"(b1));
}
__device__ __forceinline__ u64 pack2f(float lo, float hi) {
    u64 r; asm("mov.b64 %0, {%1, %2};" : "=l"(r) : "f"(lo), "f"(hi)); return r;
}
__device__ __forceinline__ void unpack2f(u64 v, float& lo, float& hi) {
    asm("mov.b64 {%0, %1}, %2;" : "=f"(lo), "=f"(hi) : "l"(v));
}
__device__ __forceinline__ u64 ffma2(u64 a, u64 b, u64 c) {
    u64 d; asm("fma.rn.f32x2 %0, %1, %2, %3;" : "=l"(d) : "l"(a), "l"(b), "l"(c)); return d;
}

// ---------------------------------------------------------------------------
// Shared tile geometry for HMMA kernels
// ---------------------------------------------------------------------------
#define DEC_TILE_B  10240
#define DEC_STAGE_B (4 * DEC_TILE_B)
#define DEC_SMEM    (2 * DEC_STAGE_B)

// ---------------------------------------------------------------------------
// ENCODER GEMM: fp16 2-plane, 3 products with fragment reuse.
// per k-slice: af<-Ah, bg<-Bh -> p0; bg2<-Bm -> p1 (af reused);
// af<-Am -> p2 (bg reused). 12 unique ldmatrix instead of 18.
// ---------------------------------------------------------------------------
template <bool RELU, bool OUTPLANES>
__global__ __launch_bounds__(256, 2)
void enc_hmma_kernel(const f16* __restrict__ Ah, const f16* __restrict__ Am,
                     const f16* __restrict__ Bh, const f16* __restrict__ Bm,
                     const float* __restrict__ bias,
                     float* __restrict__ Cf,
                     f16* __restrict__ Ch, f16* __restrict__ Cm,
                     int N, int K) {
    extern __shared__ char dsm[];
    const uint32_t su = smem_u32(dsm);

    const int tid = threadIdx.x;
    const int wid = tid >> 5, lane = tid & 31;
    const int wm = wid >> 2, wn = wid & 3;
    const int bn = blockIdx.x * 128, bm = blockIdx.y * 128;
    const int KC = K >> 5;

    const f16* P[4] = { Ah + (size_t)bm * K, Am + (size_t)bm * K,
                        Bh + (size_t)bn * K, Bm + (size_t)bn * K };

    float acc[4][4][4];
#pragma unroll
    for (int i = 0; i < 4; i++)
#pragma unroll
        for (int j = 0; j < 4; j++)
#pragma unroll
            for (int q = 0; q < 4; q++) acc[i][j][q] = 0.0f;

    auto load_chunk = [&](int stage, int k0) {
#pragma unroll
        for (int t = 0; t < 4; t++) {
            const f16* src = P[t];
#pragma unroll
            for (int j = 0; j < 2; j++) {
                int ch = j * 256 + tid;
                int r = ch >> 2, cc = ch & 3;
                uint32_t off = (uint32_t)((stage * 4 + t) * DEC_TILE_B + r * 80 + cc * 16);
                cp16(su + off, src + (size_t)r * K + k0 + cc * 8);
            }
        }
        CP_COMMIT();
    };

    load_chunk(0, 0);

    for (int c = 0; c < KC; c++) {
        CP_WAIT0();
        __syncthreads();
        if (c + 1 < KC) load_chunk((c + 1) & 1, (c + 1) << 5);

        const int stage = c & 1;
        const uint32_t bAh = su + (uint32_t)((stage * 4 + 0) * DEC_TILE_B);
        const uint32_t bAm = su + (uint32_t)((stage * 4 + 1) * DEC_TILE_B);
        const uint32_t bBh = su + (uint32_t)((stage * 4 + 2) * DEC_TILE_B);
        const uint32_t bBm = su + (uint32_t)((stage * 4 + 3) * DEC_TILE_B);

#pragma unroll
        for (int ks = 0; ks < 2; ks++) {
            const uint32_t aoff = (uint32_t)((wm * 64 + ((lane >> 3) & 1) * 8 + (lane & 7)) * 80
                                             + (ks * 16 + (lane >> 4) * 8) * 2);
            const uint32_t boff = (uint32_t)((wn * 32 + ((lane >> 4) & 1) * 8 + (lane & 7)) * 80
                                             + (ks * 16 + ((lane >> 3) & 1) * 8) * 2);
            uint32_t af[4][4], bg[2][4], bg2[2][4];

#pragma unroll
            for (int mt = 0; mt < 4; mt++) ldm_x4(af[mt], bAh + aoff + (uint32_t)(mt * 16 * 80));
#pragma unroll
            for (int np = 0; np < 2; np++) ldm_x4(bg[np], bBh + boff + (uint32_t)(np * 16 * 80));
#pragma unroll
            for (int mt = 0; mt < 4; mt++)
#pragma unroll
                for (int nt = 0; nt < 4; nt++)
                    mma_f16(acc[mt][nt], af[mt], bg[nt >> 1][(nt & 1) * 2], bg[nt >> 1][(nt & 1) * 2 + 1]);
#pragma unroll
            for (int np = 0; np < 2; np++) ldm_x4(bg2[np], bBm + boff + (uint32_t)(np * 16 * 80));
#pragma unroll
            for (int mt = 0; mt < 4; mt++)
#pragma unroll
                for (int nt = 0; nt < 4; nt++)
                    mma_f16(acc[mt][nt], af[mt], bg2[nt >> 1][(nt & 1) * 2], bg2[nt >> 1][(nt & 1) * 2 + 1]);
#pragma unroll
            for (int mt = 0; mt < 4; mt++) ldm_x4(af[mt], bAm + aoff + (uint32_t)(mt * 16 * 80));
#pragma unroll
            for (int mt = 0; mt < 4; mt++)
#pragma unroll
                for (int nt = 0; nt < 4; nt++)
                    mma_f16(acc[mt][nt], af[mt], bg[nt >> 1][(nt & 1) * 2], bg[nt >> 1][(nt & 1) * 2 + 1]);
        }
        __syncthreads();
    }

#pragma unroll
    for (int mt = 0; mt < 4; mt++) {
#pragma unroll
        for (int nt = 0; nt < 4; nt++) {
            const int r0 = bm + wm * 64 + mt * 16 + (lane >> 2);
            const int c0 = bn + wn * 32 + nt * 8 + (lane & 3) * 2;
            const float bv0 = bias[c0], bv1 = bias[c0 + 1];
#pragma unroll
            for (int h = 0; h < 2; h++) {
                const int r = r0 + h * 8;
                float v0 = acc[mt][nt][h * 2 + 0] + bv0;
                float v1 = acc[mt][nt][h * 2 + 1] + bv1;
                if (RELU) { v0 = fmaxf(v0, 0.0f); v1 = fmaxf(v1, 0.0f); }
                const size_t o = (size_t)r * N + c0;
                if (!OUTPLANES) {
                    *reinterpret_cast<float2*>(Cf + o) = make_float2(v0, v1);
                } else {
                    f16 h0 = __float2half_rn(v0), h1v = __float2half_rn(v1);
                    float r0f = v0 - __half2float(h0);
                    float r1f = v1 - __half2float(h1v);
                    __half2 hp; hp.x = h0; hp.y = h1v;
                    __half2 mp; mp.x = __float2half_rn(r0f); mp.y = __float2half_rn(r1f);
                    *reinterpret_cast<__half2*>(Ch + o) = hp;
                    *reinterpret_cast<__half2*>(Cm + o) = mp;
                }
            }
        }
    }
}

// ---------------------------------------------------------------------------
// DECODER GEMM: bf16 2-plane, 3 products with fragment reuse (bf16 required:
// decoder activations are tiny; fp16 subnormal cliff costs ~1.2e-3).
// ---------------------------------------------------------------------------
template <bool RELU, int OUTP>
__global__ __launch_bounds__(256, 2)
void gemm_hmma_kernel(const bf16* __restrict__ A0, const bf16* __restrict__ A1,
                      const bf16* __restrict__ B0, const bf16* __restrict__ B1,
                      const float* __restrict__ bias,
                      float* __restrict__ Cf,
                      bf16* __restrict__ Ch, bf16* __restrict__ Cm,
                      int N, int K) {
    extern __shared__ char dsm[];
    const uint32_t su = smem_u32(dsm);

    const int tid = threadIdx.x;
    const int wid = tid >> 5, lane = tid & 31;
    const int wm = wid >> 2, wn = wid & 3;
    const int bn = blockIdx.x * 128, bm = blockIdx.y * 128;
    const int KC = K >> 5;

    const bf16* P[4] = { A0 + (size_t)bm * K, A1 + (size_t)bm * K,
                         B0 + (size_t)bn * K, B1 + (size_t)bn * K };

    float acc[4][4][4];
#pragma unroll
    for (int i = 0; i < 4; i++)
#pragma unroll
        for (int j = 0; j < 4; j++)
#pragma unroll
            for (int q = 0; q < 4; q++) acc[i][j][q] = 0.0f;

    auto load_chunk = [&](int stage, int k0) {
#pragma unroll
        for (int t = 0; t < 4; t++) {
            const bf16* src = P[t];
#pragma unroll
            for (int j = 0; j < 2; j++) {
                int ch = j * 256 + tid;
                int r = ch >> 2, cc = ch & 3;
                uint32_t off = (uint32_t)((stage * 4 + t) * DEC_TILE_B + r * 80 + cc * 16);
                cp16(su + off, src + (size_t)r * K + k0 + cc * 8);
            }
        }
        CP_COMMIT();
    };

    load_chunk(0, 0);

    for (int c = 0; c < KC; c++) {
        CP_WAIT0();
        __syncthreads();
        if (c + 1 < KC) load_chunk((c + 1) & 1, (c + 1) << 5);

        const int stage = c & 1;
        const uint32_t bAh = su + (uint32_t)((stage * 4 + 0) * DEC_TILE_B);
        const uint32_t bAm = su + (uint32_t)((stage * 4 + 1) * DEC_TILE_B);
        const uint32_t bBh = su + (uint32_t)((stage * 4 + 2) * DEC_TILE_B);
        const uint32_t bBm = su + (uint32_t)((stage * 4 + 3) * DEC_TILE_B);

#pragma unroll
        for (int ks = 0; ks < 2; ks++) {
            const uint32_t aoff = (uint32_t)((wm * 64 + ((lane >> 3) & 1) * 8 + (lane & 7)) * 80
                                             + (ks * 16 + (lane >> 4) * 8) * 2);
            const uint32_t boff = (uint32_t)((wn * 32 + ((lane >> 4) & 1) * 8 + (lane & 7)) * 80
                                             + (ks * 16 + ((lane >> 3) & 1) * 8) * 2);
            uint32_t af[4][4], bg[2][4], bg2[2][4];

#pragma unroll
            for (int mt = 0; mt < 4; mt++) ldm_x4(af[mt], bAh + aoff + (uint32_t)(mt * 16 * 80));
#pragma unroll
            for (int np = 0; np < 2; np++) ldm_x4(bg[np], bBh + boff + (uint32_t)(np * 16 * 80));
#pragma unroll
            for (int mt = 0; mt < 4; mt++)
#pragma unroll
                for (int nt = 0; nt < 4; nt++)
                    mma_bf16(acc[mt][nt], af[mt], bg[nt >> 1][(nt & 1) * 2], bg[nt >> 1][(nt & 1) * 2 + 1]);
#pragma unroll
            for (int np = 0; np < 2; np++) ldm_x4(bg2[np], bBm + boff + (uint32_t)(np * 16 * 80));
#pragma unroll
            for (int mt = 0; mt < 4; mt++)
#pragma unroll
                for (int nt = 0; nt < 4; nt++)
                    mma_bf16(acc[mt][nt], af[mt], bg2[nt >> 1][(nt & 1) * 2], bg2[nt >> 1][(nt & 1) * 2 + 1]);
#pragma unroll
            for (int mt = 0; mt < 4; mt++) ldm_x4(af[mt], bAm + aoff + (uint32_t)(mt * 16 * 80));
#pragma unroll
            for (int mt = 0; mt < 4; mt++)
#pragma unroll
                for (int nt = 0; nt < 4; nt++)
                    mma_bf16(acc[mt][nt], af[mt], bg[nt >> 1][(nt & 1) * 2], bg[nt >> 1][(nt & 1) * 2 + 1]);
        }
        __syncthreads();
    }

#pragma unroll
    for (int mt = 0; mt < 4; mt++) {
#pragma unroll
        for (int nt = 0; nt < 4; nt++) {
            const int r0 = bm + wm * 64 + mt * 16 + (lane >> 2);
            const int c0 = bn + wn * 32 + nt * 8 + (lane & 3) * 2;
            const float bv0 = bias[c0], bv1 = bias[c0 + 1];
#pragma unroll
            for (int h = 0; h < 2; h++) {
                const int r = r0 + h * 8;
                float v0 = acc[mt][nt][h * 2 + 0] + bv0;
                float v1 = acc[mt][nt][h * 2 + 1] + bv1;
                if (RELU) { v0 = fmaxf(v0, 0.0f); v1 = fmaxf(v1, 0.0f); }
                const size_t o = (size_t)r * N + c0;
                if (OUTP == 0) {
                    *reinterpret_cast<float2*>(Cf + o) = make_float2(v0, v1);
                } else {
                    bf16 h0 = __float2bfloat16(v0), h1v = __float2bfloat16(v1);
                    float r0f = v0 - __bfloat162float(h0);
                    float r1f = v1 - __bfloat162float(h1v);
                    __nv_bfloat162 hp; hp.x = h0; hp.y = h1v;
                    __nv_bfloat162 mp; mp.x = __float2bfloat16(r0f); mp.y = __float2bfloat16(r1f);
                    *reinterpret_cast<__nv_bfloat162*>(Ch + o) = hp;
                    *reinterpret_cast<__nv_bfloat162*>(Cm + o) = mp;
                }
            }
        }
    }
}

// ---------------------------------------------------------------------------
// Splits
// ---------------------------------------------------------------------------
__global__ void split2h_kernel(const float* __restrict__ src,
                               f16* __restrict__ h, f16* __restrict__ m, int n) {
    int i = blockIdx.x * blockDim.x + threadIdx.x;
    if (i < n) {
        float v = src[i];
        f16 a = __float2half_rn(v);
        float r1 = v - __half2float(a);
        h[i] = a; m[i] = __float2half_rn(r1);
    }
}
__global__ void split2_kernel(const float* __restrict__ src,
                              bf16* __restrict__ h, bf16* __restrict__ m, int n) {
    int i = blockIdx.x * blockDim.x + threadIdx.x;
    if (i < n) {
        float v = src[i];
        bf16 a = __float2bfloat16(v);
        float r1 = v - __bfloat162float(a);
        h[i] = a; m[i] = __float2bfloat16(r1);
    }
}

// ---------------------------------------------------------------------------
// Codebook squared norms
// ---------------------------------------------------------------------------
__global__ void cnorm_kernel(const float* __restrict__ cb, float* __restrict__ cn) {
    int i = blockIdx.x * blockDim.x + threadIdx.x;
    if (i >= EMB_NUM) return;
    const float4* p = reinterpret_cast<const float4*>(cb + (size_t)i * EMB_DIM);
    float s = 0.0f;
#pragma unroll
    for (int d = 0; d < EMB_DIM / 4; d++) {
        float4 v = p[d];
        s += v.x * v.x + v.y * v.y + v.z * v.z + v.w * v.w;
    }
    cn[i] = s;
}

// ---------------------------------------------------------------------------
// VQ with gap test (proven); outputs zq as bf16 planes.
// ---------------------------------------------------------------------------
__global__ __launch_bounds__(256)
void vq_kernel(const float* __restrict__ z,
               const float* __restrict__ cb,
               const float* __restrict__ cn,
               bf16* __restrict__ qh, bf16* __restrict__ qm,
               int* __restrict__ flags) {
    constexpr int CHUNK = 128;
    __shared__ float sc[CHUNK][EMB_DIM];
    __shared__ float scn[CHUNK];

    const int row = blockIdx.x * blockDim.x + threadIdx.x;
    const float* zp = z + (size_t)row * EMB_DIM;

    u64 m2zP[EMB_DIM / 2];
#pragma unroll
    for (int d = 0; d < EMB_DIM / 4; d++) {
        float4 v = reinterpret_cast<const float4*>(zp)[d];
        m2zP[d * 2 + 0] = pack2f(-2.0f * v.x, -2.0f * v.y);
        m2zP[d * 2 + 1] = pack2f(-2.0f * v.z, -2.0f * v.w);
    }

    float best = 3.0e38f, best2 = 3.0e38f;
    int bidx = 0;
    for (int ch = 0; ch < EMB_NUM / CHUNK; ch++) {
        __syncthreads();
        const float4* src = reinterpret_cast<const float4*>(cb + (size_t)ch * CHUNK * EMB_DIM);
        float4* dst = reinterpret_cast<float4*>(&sc[0][0]);
        for (int i = threadIdx.x; i < CHUNK * EMB_DIM / 4; i += 256) dst[i] = src[i];
        if (threadIdx.x < CHUNK) scn[threadIdx.x] = cn[ch * CHUNK + threadIdx.x];
        __syncthreads();

        for (int j = 0; j < CHUNK; j++) {
            const u64* cc8 = reinterpret_cast<const u64*>(&sc[j][0]);
            u64 sP = 0ull;
#pragma unroll
            for (int d = 0; d < EMB_DIM / 2; d++)
                sP = ffma2(cc8[d], m2zP[d], sP);
            float lo, hi;
            unpack2f(sP, lo, hi);
            float s = scn[j] + lo + hi;
            if (s < best) { best2 = best; best = s; bidx = ch * CHUNK + j; }
            else if (s < best2) { best2 = s; }
        }
    }

    flags[row] = (best2 - best < FLAG_T) ? 1 : 0;

    const float* cp = cb + (size_t)bidx * EMB_DIM;
#pragma unroll
    for (int d = 0; d < EMB_DIM; d++) {
        float zz = zp[d];
        float v = zz + (cp[d] - zz);
        bf16 a = __float2bfloat16(v);
        float r1 = v - __bfloat162float(a);
        size_t o = (size_t)row * EMB_DIM + d;
        qh[o] = a; qm[o] = __float2bfloat16(r1);
    }
}

// ---------------------------------------------------------------------------
// Repair list: reset + compact flagged x-rows
// ---------------------------------------------------------------------------
__global__ void rep_reset_kernel(int* nrep) { *nrep = 0; }

__global__ void rep_compact_kernel(const int* __restrict__ flags,
                                   int* __restrict__ rlist, int* __restrict__ nrep) {
    int row = blockIdx.x * blockDim.x + threadIdx.x;
    if (row >= M_ROWS) return;
    const int f = flags[row * 4 + 0] | flags[row * 4 + 1] | flags[row * 4 + 2] | flags[row * 4 + 3];
    if (f) {
        int pos = atomicAdd(nrep, 1);
        if (pos < REP_CAP) rlist[pos] = row;
    }
}

// ---------------------------------------------------------------------------
// Batched repair phase 1: exact h1 for listed rows (proven)
// ---------------------------------------------------------------------------
__global__ __launch_bounds__(256)
void rep_h1_kernel(const float* __restrict__ x,
                   const float* __restrict__ w0, const float* __restrict__ b0,
                   const int* __restrict__ rlist, const int* __restrict__ nrep,
                   float* __restrict__ rh1) {
    __shared__ float xs[8][2048];
    const int nr = min(*nrep, REP_CAP);
    const int t = threadIdx.x;
    const int out = blockIdx.x * 256 + t;
    const float* wr = w0 + (size_t)out * 2048;
    const float bb = b0[out];

    for (int base = blockIdx.y * 8; base < nr; base += gridDim.y * 8) {
        const int cnt = min(8, nr - base);
        __syncthreads();
        for (int r = 0; r < cnt; r++) {
            const float4* xr = reinterpret_cast<const float4*>(x + (size_t)rlist[base + r] * 2048);
            float4* xd = reinterpret_cast<float4*>(xs[r]);
            for (int i = t; i < 512; i += 256) xd[i] = xr[i];
        }
        __syncthreads();
        float acc[8];
#pragma unroll
        for (int r = 0; r < 8; r++) acc[r] = 0.0f;
        for (int k = 0; k < 2048; k += 4) {
            float4 wv = *reinterpret_cast<const float4*>(wr + k);
#pragma unroll
            for (int r = 0; r < 8; r++) {
                float4 xv = *reinterpret_cast<const float4*>(&xs[r][k]);
                acc[r] = fmaf(xv.x, wv.x, acc[r]);
                acc[r] = fmaf(xv.y, wv.y, acc[r]);
                acc[r] = fmaf(xv.z, wv.z, acc[r]);
                acc[r] = fmaf(xv.w, wv.w, acc[r]);
            }
        }
        for (int r = 0; r < cnt; r++)
            rh1[(size_t)(base + r) * 1024 + out] = fmaxf(acc[r] + bb, 0.0f);
    }
}

// ---------------------------------------------------------------------------
// Batched repair phase 2: exact h2 from rh1 (proven)
// ---------------------------------------------------------------------------
__global__ __launch_bounds__(256)
void rep_h2_kernel(const float* __restrict__ w1, const float* __restrict__ b1,
                   const int* __restrict__ nrep,
                   const float* __restrict__ rh1, float* __restrict__ rh2) {
    __shared__ float hs[8][1024];
    const int nr = min(*nrep, REP_CAP);
    const int t = threadIdx.x;
    const int out = blockIdx.x * 256 + t;
    const float* wr = w1 + (size_t)out * 1024;
    const float bb = b1[out];

    for (int base = blockIdx.y * 8; base < nr; base += gridDim.y * 8) {
        const int cnt = min(8, nr - base);
        __syncthreads();
        for (int r = 0; r < cnt; r++) {
            const float4* hr = reinterpret_cast<const float4*>(rh1 + (size_t)(base + r) * 1024);
            float4* hd = reinterpret_cast<float4*>(hs[r]);
            for (int i = t; i < 256; i += 256) hd[i] = hr[i];
        }
        __syncthreads();
        float acc[8];
#pragma unroll
        for (int r = 0; r < 8; r++) acc[r] = 0.0f;
        for (int k = 0; k < 1024; k += 4) {
            float4 wv = *reinterpret_cast<const float4*>(wr + k);
#pragma unroll
            for (int r = 0; r < 8; r++) {
                float4 hv = *reinterpret_cast<const float4*>(&hs[r][k]);
                acc[r] = fmaf(hv.x, wv.x, acc[r]);
                acc[r] = fmaf(hv.y, wv.y, acc[r]);
                acc[r] = fmaf(hv.z, wv.z, acc[r]);
                acc[r] = fmaf(hv.w, wv.w, acc[r]);
            }
        }
        for (int r = 0; r < cnt; r++)
            rh2[(size_t)(base + r) * 512 + out] = fmaxf(acc[r] + bb, 0.0f);
    }
}

// ---------------------------------------------------------------------------
// Batched repair phase 3: exact z + exact argmin + zq write (bf16 planes)
// ---------------------------------------------------------------------------
__global__ __launch_bounds__(256)
void rep_z_kernel(const float* __restrict__ zw, const float* __restrict__ zb,
                  const float* __restrict__ cb, const float* __restrict__ cn,
                  const int* __restrict__ rlist, const int* __restrict__ nrep,
                  const int* __restrict__ flags,
                  const float* __restrict__ rh2,
                  bf16* __restrict__ qh, bf16* __restrict__ qm) {
    __shared__ float h2s[512];
    __shared__ float zs[256];
    __shared__ float rbest[256];
    __shared__ int ridx[256];
    const int nr = min(*nrep, REP_CAP);
    const int t = threadIdx.x;

    for (int pos = blockIdx.x; pos < nr; pos += gridDim.x) {
        const int row = rlist[pos];
        __syncthreads();
        {
            const float4* hr = reinterpret_cast<const float4*>(rh2 + (size_t)pos * 512);
            float4* hd = reinterpret_cast<float4*>(h2s);
            for (int i = t; i < 128; i += 256) hd[i] = hr[i];
        }
        __syncthreads();
        {
            const float* wr = zw + (size_t)t * 512;
            float acc = 0.0f;
            for (int k = 0; k < 512; k += 4) {
                float4 hv = *reinterpret_cast<const float4*>(h2s + k);
                float4 wv = *reinterpret_cast<const float4*>(wr + k);
                acc = fmaf(hv.x, wv.x, acc); acc = fmaf(hv.y, wv.y, acc);
                acc = fmaf(hv.z, wv.z, acc); acc = fmaf(hv.w, wv.w, acc);
            }
            zs[t] = acc + zb[t];
        }
        __syncthreads();

#pragma unroll
        for (int g = 0; g < 4; g++) {
            if (!flags[row * 4 + g]) continue;
            const float* zg = zs + g * EMB_DIM;
            u64 m2zP[EMB_DIM / 2];
#pragma unroll
            for (int d = 0; d < EMB_DIM / 4; d++) {
                float4 v = *reinterpret_cast<const float4*>(zg + d * 4);
                m2zP[d * 2 + 0] = pack2f(-2.0f * v.x, -2.0f * v.y);
                m2zP[d * 2 + 1] = pack2f(-2.0f * v.z, -2.0f * v.w);
            }
            float best = 3.0e38f;
            int bidx = 0;
            for (int jj = 0; jj < 4; jj++) {
                int j = jj * 256 + t;
                u64 sP = 0ull;
                const u64* cc8 = reinterpret_cast<const u64*>(cb + (size_t)j * EMB_DIM);
#pragma unroll
                for (int d = 0; d < EMB_DIM / 2; d++)
                    sP = ffma2(cc8[d], m2zP[d], sP);
                float lo, hi;
                unpack2f(sP, lo, hi);
                float s = cn[j] + lo + hi;
                if (s < best || (s == best && j < bidx)) { best = s; bidx = j; }
            }
            rbest[t] = best; ridx[t] = bidx;
            __syncthreads();
            for (int s2 = 128; s2 > 0; s2 >>= 1) {
                if (t < s2) {
                    float ob = rbest[t + s2]; int oi = ridx[t + s2];
                    if (ob < rbest[t] || (ob == rbest[t] && oi < ridx[t])) { rbest[t] = ob; ridx[t] = oi; }
                }
                __syncthreads();
            }
            const int fin = ridx[0];
            if (t < EMB_DIM) {
                float zz = zg[t];
                float v = zz + (cb[(size_t)fin * EMB_DIM + t] - zz);
                bf16 a = __float2bfloat16(v);
                float r1 = v - __bfloat162float(a);
                size_t o = ((size_t)row * 4 + g) * EMB_DIM + t;
                qh[o] = a; qm[o] = __float2bfloat16(r1);
            }
            __syncthreads();
        }
    }
}

// ---------------------------------------------------------------------------
// FALLBACK per-row repair (active only if nrep > REP_CAP)
// ---------------------------------------------------------------------------
__global__ __launch_bounds__(256)
void repair_kernel(const float* __restrict__ x,
                   const float* __restrict__ w0, const float* __restrict__ b0,
                   const float* __restrict__ w1, const float* __restrict__ b1,
                   const float* __restrict__ zw, const float* __restrict__ zb,
                   const float* __restrict__ cb, const float* __restrict__ cn,
                   const int* __restrict__ flags, const int* __restrict__ nrep,
                   bf16* __restrict__ qh, bf16* __restrict__ qm) {
    if (*nrep <= REP_CAP) return;
    const int row = blockIdx.x;
    const int f0 = flags[row * 4 + 0], f1 = flags[row * 4 + 1];
    const int f2 = flags[row * 4 + 2], f3 = flags[row * 4 + 3];
    if (!(f0 | f1 | f2 | f3)) return;

    __shared__ float xs[2048];
    __shared__ float h1s[1024];
    __shared__ float h2s[512];
    __shared__ float zs[256];
    __shared__ float rbest[256];
    __shared__ int ridx[256];

    const int t = threadIdx.x;

    {
        const float4* xr = reinterpret_cast<const float4*>(x + (size_t)row * 2048);
        float4* xd = reinterpret_cast<float4*>(xs);
        for (int i = t; i < 512; i += 256) xd[i] = xr[i];
    }
    __syncthreads();

    {
        const float* r0 = w0 + (size_t)(t      ) * 2048;
        const float* r1 = w0 + (size_t)(t + 256) * 2048;
        const float* r2 = w0 + (size_t)(t + 512) * 2048;
        const float* r3 = w0 + (size_t)(t + 768) * 2048;
        float a0 = 0.0f, a1 = 0.0f, a2 = 0.0f, a3 = 0.0f;
        for (int k = 0; k < 2048; k += 4) {
            float4 xv = *reinterpret_cast<const float4*>(xs + k);
            float4 v0 = *reinterpret_cast<const float4*>(r0 + k);
            float4 v1 = *reinterpret_cast<const float4*>(r1 + k);
            float4 v2 = *reinterpret_cast<const float4*>(r2 + k);
            float4 v3 = *reinterpret_cast<const float4*>(r3 + k);
            a0 = fmaf(xv.x, v0.x, a0); a0 = fmaf(xv.y, v0.y, a0);
            a0 = fmaf(xv.z, v0.z, a0); a0 = fmaf(xv.w, v0.w, a0);
            a1 = fmaf(xv.x, v1.x, a1); a1 = fmaf(xv.y, v1.y, a1);
            a1 = fmaf(xv.z, v1.z, a1); a1 = fmaf(xv.w, v1.w, a1);
            a2 = fmaf(xv.x, v2.x, a2); a2 = fmaf(xv.y, v2.y, a2);
            a2 = fmaf(xv.z, v2.z, a2); a2 = fmaf(xv.w, v2.w, a2);
            a3 = fmaf(xv.x, v3.x, a3); a3 = fmaf(xv.y, v3.y, a3);
            a3 = fmaf(xv.z, v3.z, a3); a3 = fmaf(xv.w, v3.w, a3);
        }
        h1s[t      ] = fmaxf(a0 + b0[t      ], 0.0f);
        h1s[t + 256] = fmaxf(a1 + b0[t + 256], 0.0f);
        h1s[t + 512] = fmaxf(a2 + b0[t + 512], 0.0f);
        h1s[t + 768] = fmaxf(a3 + b0[t + 768], 0.0f);
    }
    __syncthreads();

    {
        const float* r0 = w1 + (size_t)(t      ) * 1024;
        const float* r1 = w1 + (size_t)(t + 256) * 1024;
        float a0 = 0.0f, a1 = 0.0f;
        for (int k = 0; k < 1024; k += 4) {
            float4 hv = *reinterpret_cast<const float4*>(h1s + k);
            float4 v0 = *reinterpret_cast<const float4*>(r0 + k);
            float4 v1 = *reinterpret_cast<const float4*>(r1 + k);
            a0 = fmaf(hv.x, v0.x, a0); a0 = fmaf(hv.y, v0.y, a0);
            a0 = fmaf(hv.z, v0.z, a0); a0 = fmaf(hv.w, v0.w, a0);
            a1 = fmaf(hv.x, v1.x, a1); a1 = fmaf(hv.y, v1.y, a1);
            a1 = fmaf(hv.z, v1.z, a1); a1 = fmaf(hv.w, v1.w, a1);
        }
        h2s[t      ] = fmaxf(a0 + b1[t      ], 0.0f);
        h2s[t + 256] = fmaxf(a1 + b1[t + 256], 0.0f);
    }
    __syncthreads();

    {
        const float* wr = zw + (size_t)t * 512;
        float acc = 0.0f;
        for (int k = 0; k < 512; k += 4) {
            float4 hv = *reinterpret_cast<const float4*>(h2s + k);
            float4 wv = *reinterpret_cast<const float4*>(wr + k);
            acc = fmaf(hv.x, wv.x, acc); acc = fmaf(hv.y, wv.y, acc);
            acc = fmaf(hv.z, wv.z, acc); acc = fmaf(hv.w, wv.w, acc);
        }
        zs[t] = acc + zb[t];
    }
    __syncthreads();

    const int gf[4] = {f0, f1, f2, f3};
#pragma unroll
    for (int g = 0; g < 4; g++) {
        if (!gf[g]) continue;
        const float* zg = zs + g * EMB_DIM;
        u64 m2zP[EMB_DIM / 2];
#pragma unroll
        for (int d = 0; d < EMB_DIM / 4; d++) {
            float4 v = *reinterpret_cast<const float4*>(zg + d * 4);
            m2zP[d * 2 + 0] = pack2f(-2.0f * v.x, -2.0f * v.y);
            m2zP[d * 2 + 1] = pack2f(-2.0f * v.z, -2.0f * v.w);
        }
        float best = 3.0e38f;
        int bidx = 0;
        for (int jj = 0; jj < 4; jj++) {
            int j = jj * 256 + t;
            u64 sP = 0ull;
            const u64* cc8 = reinterpret_cast<const u64*>(cb + (size_t)j * EMB_DIM);
#pragma unroll
            for (int d = 0; d < EMB_DIM / 2; d++)
                sP = ffma2(cc8[d], m2zP[d], sP);
            float lo, hi;
            unpack2f(sP, lo, hi);
            float s = cn[j] + lo + hi;
            if (s < best || (s == best && j < bidx)) { best = s; bidx = j; }
        }
        rbest[t] = best; ridx[t] = bidx;
        __syncthreads();
        for (int s2 = 128; s2 > 0; s2 >>= 1) {
            if (t < s2) {
                float ob = rbest[t + s2]; int oi = ridx[t + s2];
                if (ob < rbest[t] || (ob == rbest[t] && oi < ridx[t])) { rbest[t] = ob; ridx[t] = oi; }
            }
            __syncthreads();
        }
        const int fin = ridx[0];
        if (t < EMB_DIM) {
            float zz = zg[t];
            float v = zz + (cb[(size_t)fin * EMB_DIM + t] - zz);
            bf16 a = __float2bfloat16(v);
            float r1 = v - __bfloat162float(a);
            size_t o = ((size_t)row * 4 + g) * EMB_DIM + t;
            qh[o] = a; qm[o] = __float2bfloat16(r1);
        }
        __syncthreads();
    }
}

// ---------------------------------------------------------------------------
// Host launch
// ---------------------------------------------------------------------------
template <bool RELU, bool OUTPLANES>
static inline void launch_encH(const f16* Ah, const f16* Am,
                               const f16* Bh, const f16* Bm,
                               const float* bias, float* Cf, f16* Ch, f16* Cm,
                               int N, int K) {
    cudaFuncSetAttribute(enc_hmma_kernel<RELU, OUTPLANES>,
                         cudaFuncAttributeMaxDynamicSharedMemorySize, DEC_SMEM);
    dim3 grid(N / 128, M_ROWS / 128);
    enc_hmma_kernel<RELU, OUTPLANES><<<grid, 256, DEC_SMEM>>>(Ah, Am, Bh, Bm, bias, Cf, Ch, Cm, N, K);
}

template <bool RELU, int OUTP>
static inline void launch_dec(const bf16* A0, const bf16* A1,
                              const bf16* B0, const bf16* B1,
                              const float* bias, float* Cf, bf16* Ch, bf16* Cm,
                              int N, int K) {
    cudaFuncSetAttribute(gemm_hmma_kernel<RELU, OUTP>,
                         cudaFuncAttributeMaxDynamicSharedMemorySize, DEC_SMEM);
    dim3 grid(N / 128, M_ROWS / 128);
    gemm_hmma_kernel<RELU, OUTP><<<grid, 256, DEC_SMEM>>>(A0, A1, B0, B1, bias, Cf, Ch, Cm, N, K);
}

extern "C" void kernel_launch(void* const* d_in, const int* in_sizes, int n_in,
                              void* d_out, int out_size) {
    const float* x        = (const float*)d_in[0];
    const float* enc0_w   = (const float*)d_in[1];
    const float* enc0_b   = (const float*)d_in[2];
    const float* enc1_w   = (const float*)d_in[3];
    const float* enc1_b   = (const float*)d_in[4];
    const float* z_w      = (const float*)d_in[5];
    const float* z_b      = (const float*)d_in[6];
    const float* codebook = (const float*)d_in[7];
    const float* dec0_w   = (const float*)d_in[8];
    const float* dec0_b   = (const float*)d_in[9];
    const float* dec1_w   = (const float*)d_in[10];
    const float* dec1_b   = (const float*)d_in[11];
    const float* out_w    = (const float*)d_in[12];
    const float* out_b    = (const float*)d_in[13];
    float* out = (float*)d_out;

    f16 *xh, *xm, *w0h, *w0m, *w1h, *w1m, *wzh, *wzm, *h1h, *h1m, *h2h, *h2m;
    cudaGetSymbolAddress((void**)&xh, g_xh);
    cudaGetSymbolAddress((void**)&xm, g_xm);
    cudaGetSymbolAddress((void**)&w0h, g_w0h);
    cudaGetSymbolAddress((void**)&w0m, g_w0m);
    cudaGetSymbolAddress((void**)&w1h, g_w1h);
    cudaGetSymbolAddress((void**)&w1m, g_w1m);
    cudaGetSymbolAddress((void**)&wzh, g_wzh);
    cudaGetSymbolAddress((void**)&wzm, g_wzm);
    cudaGetSymbolAddress((void**)&h1h, g_h1h);
    cudaGetSymbolAddress((void**)&h1m, g_h1m);
    cudaGetSymbolAddress((void**)&h2h, g_h2h);
    cudaGetSymbolAddress((void**)&h2m, g_h2m);
    float *z, *cn, *rh1, *rh2;
    int *flags, *rlist, *nrep;
    cudaGetSymbolAddress((void**)&z,  g_z);
    cudaGetSymbolAddress((void**)&cn, g_cn);
    cudaGetSymbolAddress((void**)&flags, g_flags);
    cudaGetSymbolAddress((void**)&rlist, g_rlist);
    cudaGetSymbolAddress((void**)&nrep, g_nrep);
    cudaGetSymbolAddress((void**)&rh1, g_rh1);
    cudaGetSymbolAddress((void**)&rh2, g_rh2);
    bf16 (*zq)[8192 * 256];   cudaGetSymbolAddress((void**)&zq, g_zq);
    bf16 (*d1)[8192 * 512];   cudaGetSymbolAddress((void**)&d1, g_d1);
    bf16 (*d2)[8192 * 1024];  cudaGetSymbolAddress((void**)&d2, g_d2);
    bf16 (*wd0)[512 * 256];   cudaGetSymbolAddress((void**)&wd0, g_wd0);
    bf16 (*wd1)[1024 * 512];  cudaGetSymbolAddress((void**)&wd1, g_wd1);
    bf16 (*wo)[2048 * 1024];  cudaGetSymbolAddress((void**)&wo, g_wo);

    // launches 0-4 (so ncu -s 5 profiles enc h1)
    split2h_kernel<<<(8192 * 2048 + 255) / 256, 256>>>(x, xh, xm, 8192 * 2048);
    split2h_kernel<<<(1024 * 2048 + 255) / 256, 256>>>(enc0_w, w0h, w0m, 1024 * 2048);
    split2h_kernel<<<(512 * 1024 + 255) / 256, 256>>>(enc1_w, w1h, w1m, 512 * 1024);
    split2h_kernel<<<(256 * 512 + 255) / 256, 256>>>(z_w, wzh, wzm, 256 * 512);
    cnorm_kernel<<<4, 256>>>(codebook, cn);

    // encoder (launch 5 = h1): fp16 HMMA, 3 products
    launch_encH<true,  true >(xh, xm, w0h, w0m, enc0_b, nullptr, h1h, h1m, 1024, 2048);
    launch_encH<true,  true >(h1h, h1m, w1h, w1m, enc1_b, nullptr, h2h, h2m, 512, 1024);
    launch_encH<false, false>(h2h, h2m, wzh, wzm, z_b, z, nullptr, nullptr, 256, 512);

    // vector quantization with gap test
    rep_reset_kernel<<<1, 1>>>(nrep);
    vq_kernel<<<(M_ROWS * 256 / EMB_DIM) / 256, 256>>>(z, codebook, cn, zq[0], zq[1], flags);

    // batched exact repair of flagged rows
    rep_compact_kernel<<<M_ROWS / 256, 256>>>(flags, rlist, nrep);
    { dim3 g1(4, 16);  rep_h1_kernel<<<g1, 256>>>(x, enc0_w, enc0_b, rlist, nrep, rh1); }
    { dim3 g2(2, 16);  rep_h2_kernel<<<g2, 256>>>(enc1_w, enc1_b, nrep, rh1, rh2); }
    rep_z_kernel<<<64, 256>>>(z_w, z_b, codebook, cn, rlist, nrep, flags, rh2, zq[0], zq[1]);
    repair_kernel<<<M_ROWS, 256>>>(x, enc0_w, enc0_b, enc1_w, enc1_b, z_w, z_b,
                                   codebook, cn, flags, nrep, zq[0], zq[1]);

    // decoder weight splits (bf16) + decoder: bf16 HMMA, 3 products
    split2_kernel<<<(512 * 256 + 255) / 256, 256>>>(dec0_w, wd0[0], wd0[1], 512 * 256);
    split2_kernel<<<(1024 * 512 + 255) / 256, 256>>>(dec1_w, wd1[0], wd1[1], 1024 * 512);
    split2_kernel<<<(2048 * 1024 + 255) / 256, 256>>>(out_w, wo[0], wo[1], 2048 * 1024);

    launch_dec<true,  2>(zq[0], zq[1], wd0[0], wd0[1], dec0_b, nullptr, d1[0], d1[1], 512, 256);
    launch_dec<true,  2>(d1[0], d1[1], wd1[0], wd1[1], dec1_b, nullptr, d2[0], d2[1], 1024, 512);
    launch_dec<false, 0>(d2[0], d2[1], wo[0], wo[1],  out_b,  out, nullptr, nullptr, 2048, 1024);
}